// round 13
// baseline (speedup 1.0000x reference)
#include <cuda_runtime.h>
#include <cuda_fp16.h>

#define N_NODES 50000
#define N_EDGES 1000000
#define D_IN    64
#define D_HID   64
#define D_OUTF  32

// ---- scratch (no allocs). Device globals referenced ONLY in device code. ----
__device__ float  g_deg [N_NODES];
__device__ int    g_cnt [N_NODES];
__device__ int    g_rowstart[N_NODES + 1];
__device__ int    g_rank[N_EDGES];
__device__ float4 g_edge[N_EDGES];          // dst-sorted {src bits, dst bits, w, pad}
__device__ __half g_h16 [N_NODES * D_HID];  // hs = dinv*(X@W), fp16
__device__ float  g_agg [N_NODES * D_HID];  // layer-1 aggregation (fp32)

__device__ __forceinline__ void red_add_v4(float* p, float4 v) {
    asm volatile("red.global.add.v4.f32 [%0], {%1, %2, %3, %4};"
                 :: "l"(p), "f"(v.x), "f"(v.y), "f"(v.z), "f"(v.w) : "memory");
}
__device__ __forceinline__ unsigned int h2u(__half2 h) {
    return *reinterpret_cast<unsigned int*>(&h);
}

// ---------------- CSR-sort build ----------------
__global__ void k_zero() {
    int i = blockIdx.x * blockDim.x + threadIdx.x;
    if (i < N_NODES) { g_cnt[i] = 0; g_deg[i] = 1.0f; }   // deg includes self-loop
}

// rank within dst + weighted degree, one pass.
__global__ void k_hist(const int* __restrict__ dst, const float* __restrict__ w) {
    int t = blockIdx.x * blockDim.x + threadIdx.x;
    int e0 = t * 4;
#pragma unroll
    for (int j = 0; j < 4; j++) {
        int e = e0 + j;
        if (e < N_EDGES) {
            int d = __ldg(&dst[e]);
            g_rank[e] = atomicAdd(&g_cnt[d], 1);
            atomicAdd(&g_deg[d], __ldg(&w[e]));
        }
    }
}

// single-block (512 thr) exclusive scan of cnt -> rowstart. unroll 4: no spills.
__global__ __launch_bounds__(512) void k_scan() {
    constexpr int NT  = 512;
    constexpr int PER = (N_NODES + NT - 1) / NT;   // 98
    __shared__ int bs[NT];
    int t = threadIdx.x;
    int base = t * PER;

    int s = 0;
#pragma unroll 4
    for (int i = 0; i < PER; i++) {
        int idx = base + i;
        if (idx < N_NODES) s += g_cnt[idx];
    }
    bs[t] = s;
    __syncthreads();
#pragma unroll 1
    for (int off = 1; off < NT; off <<= 1) {
        int v = (t >= off) ? bs[t - off] : 0;
        __syncthreads();
        bs[t] += v;
        __syncthreads();
    }
    int run = bs[t] - s;
#pragma unroll 4
    for (int i = 0; i < PER; i++) {
        int idx = base + i;
        if (idx < N_NODES) {
            g_rowstart[idx] = run;
            run += g_cnt[idx];
            if (idx == N_NODES - 1) g_rowstart[N_NODES] = run;
        }
    }
}

// place records at rowstart[dst]+rank -> dst-sorted edge array. No atomics.
__global__ void k_place(const int* __restrict__ src, const int* __restrict__ dst,
                        const float* __restrict__ w) {
    int t = blockIdx.x * blockDim.x + threadIdx.x;
    int e0 = t * 4;
#pragma unroll
    for (int j = 0; j < 4; j++) {
        int e = e0 + j;
        if (e < N_EDGES) {
            int d = __ldg(&dst[e]);
            int p = g_rowstart[d] + g_rank[e];
            g_edge[p] = make_float4(__int_as_float(__ldg(&src[e])),
                                    __int_as_float(d), __ldg(&w[e]), 0.0f);
        }
    }
}

// ---------------- GEMM L1 (64->64): 4x8 per thread ----------------
__global__ __launch_bounds__(128) void k_gemm64(
        const float* __restrict__ X, const float* __restrict__ W) {
    constexpr int DI = 64, DO = 64;
    constexpr int TX = 8, ROWS = 64, XS = ROWS + 4;
    __shared__ float Ws [DI * DO];
    __shared__ float xsT[DI * XS];

    const int tid = threadIdx.x;
    const int tx  = tid % TX;
    const int ty  = tid / TX;
    const int blockRow = blockIdx.x * ROWS;

    for (int i = tid; i < DI * DO / 4; i += 128)
        reinterpret_cast<float4*>(Ws)[i] = reinterpret_cast<const float4*>(W)[i];

    for (int i = tid; i < ROWS * (DI / 4); i += 128) {
        int row = i / (DI / 4);
        int c4  = i % (DI / 4);
        int gr  = blockRow + row;
        float4 v = make_float4(0.f, 0.f, 0.f, 0.f);
        if (gr < N_NODES)
            v = reinterpret_cast<const float4*>(X + gr * DI)[c4];
        xsT[(c4 * 4 + 0) * XS + row] = v.x;
        xsT[(c4 * 4 + 1) * XS + row] = v.y;
        xsT[(c4 * 4 + 2) * XS + row] = v.z;
        xsT[(c4 * 4 + 3) * XS + row] = v.w;
    }
    __syncthreads();

    float acc[4][8];
#pragma unroll
    for (int i = 0; i < 4; i++)
#pragma unroll
        for (int j = 0; j < 8; j++) acc[i][j] = 0.0f;

#pragma unroll
    for (int k = 0; k < DI; k++) {
        float4 a  = *reinterpret_cast<const float4*>(&xsT[k * XS + ty * 4]);
        float4 b0 = *reinterpret_cast<const float4*>(&Ws [k * DO + tx * 8]);
        float4 b1 = *reinterpret_cast<const float4*>(&Ws [k * DO + tx * 8 + 4]);
        float av[4] = {a.x, a.y, a.z, a.w};
        float bv[8] = {b0.x, b0.y, b0.z, b0.w, b1.x, b1.y, b1.z, b1.w};
#pragma unroll
        for (int i = 0; i < 4; i++)
#pragma unroll
            for (int j = 0; j < 8; j++)
                acc[i][j] += av[i] * bv[j];
    }

#pragma unroll
    for (int i = 0; i < 4; i++) {
        int row = blockRow + ty * 4 + i;
        if (row >= N_NODES) break;
        float dv = rsqrtf(g_deg[row]);
        float v[8];
#pragma unroll
        for (int j = 0; j < 8; j++) v[j] = dv * acc[i][j];
        *reinterpret_cast<float4*>(&g_agg[row * DO + tx * 8])
            = make_float4(v[0], v[1], v[2], v[3]);
        *reinterpret_cast<float4*>(&g_agg[row * DO + tx * 8 + 4])
            = make_float4(v[4], v[5], v[6], v[7]);
        uint4 hp;
        hp.x = h2u(__float22half2_rn(make_float2(v[0], v[1])));
        hp.y = h2u(__float22half2_rn(make_float2(v[2], v[3])));
        hp.z = h2u(__float22half2_rn(make_float2(v[4], v[5])));
        hp.w = h2u(__float22half2_rn(make_float2(v[6], v[7])));
        *reinterpret_cast<uint4*>(&g_h16[row * DO + tx * 8]) = hp;
    }
}

// ---------------- GEMM L2 (64->32), input fused with final1 ----------------
__global__ __launch_bounds__(256) void k_gemm32(const float* __restrict__ W,
                                                const float* __restrict__ b1,
                                                float* __restrict__ OUT) {
    constexpr int DI = 64, DO = 32;
    constexpr int TX = 8, ROWS = 128, XS = ROWS + 4;
    __shared__ float Ws [DI * DO];
    __shared__ float xsT[DI * XS];

    const int tid = threadIdx.x;
    const int tx  = tid % TX;
    const int ty  = tid / TX;
    const int blockRow = blockIdx.x * ROWS;

    for (int i = tid; i < DI * DO / 4; i += 256)
        reinterpret_cast<float4*>(Ws)[i] = reinterpret_cast<const float4*>(W)[i];

    for (int i = tid; i < ROWS * (DI / 4); i += 256) {
        int row = i / (DI / 4);
        int c4  = i % (DI / 4);
        int gr  = blockRow + row;
        float4 v = make_float4(0.f, 0.f, 0.f, 0.f);
        if (gr < N_NODES) {
            v = reinterpret_cast<const float4*>(g_agg + gr * DI)[c4];
            float  dv = rsqrtf(g_deg[gr]);
            float4 bb = __ldg(&reinterpret_cast<const float4*>(b1)[c4]);
            v.x = fmaxf(dv * v.x + bb.x, 0.0f);
            v.y = fmaxf(dv * v.y + bb.y, 0.0f);
            v.z = fmaxf(dv * v.z + bb.z, 0.0f);
            v.w = fmaxf(dv * v.w + bb.w, 0.0f);
        }
        xsT[(c4 * 4 + 0) * XS + row] = v.x;
        xsT[(c4 * 4 + 1) * XS + row] = v.y;
        xsT[(c4 * 4 + 2) * XS + row] = v.z;
        xsT[(c4 * 4 + 3) * XS + row] = v.w;
    }
    __syncthreads();

    float acc[4][4];
#pragma unroll
    for (int i = 0; i < 4; i++)
#pragma unroll
        for (int j = 0; j < 4; j++) acc[i][j] = 0.0f;

#pragma unroll
    for (int k = 0; k < DI; k++) {
        float4 a = *reinterpret_cast<const float4*>(&xsT[k * XS + ty * 4]);
        float4 b = *reinterpret_cast<const float4*>(&Ws [k * DO + tx * 4]);
        acc[0][0] += a.x * b.x; acc[0][1] += a.x * b.y; acc[0][2] += a.x * b.z; acc[0][3] += a.x * b.w;
        acc[1][0] += a.y * b.x; acc[1][1] += a.y * b.y; acc[1][2] += a.y * b.z; acc[1][3] += a.y * b.w;
        acc[2][0] += a.z * b.x; acc[2][1] += a.z * b.y; acc[2][2] += a.z * b.z; acc[2][3] += a.z * b.w;
        acc[3][0] += a.w * b.x; acc[3][1] += a.w * b.y; acc[3][2] += a.w * b.z; acc[3][3] += a.w * b.w;
    }

#pragma unroll
    for (int i = 0; i < 4; i++) {
        int row = blockRow + ty * 4 + i;
        if (row >= N_NODES) break;
        float dv = rsqrtf(g_deg[row]);
        float4 v = make_float4(dv * acc[i][0], dv * acc[i][1],
                               dv * acc[i][2], dv * acc[i][3]);
        *reinterpret_cast<float4*>(&OUT[row * DO + tx * 4]) = v;   // self-loop init
        uint2 hp;
        hp.x = h2u(__float22half2_rn(make_float2(v.x, v.y)));
        hp.y = h2u(__float22half2_rn(make_float2(v.z, v.w)));
        *reinterpret_cast<uint2*>(&g_h16[row * DO + tx * 4]) = hp;
    }
}

// ---------------- segmented scatter over dst-sorted edges ----------------
// D=64: 16-lane groups, 16 edges/group. Records staged coalesced (1/lane),
// broadcast via shfl(width=16). One RED per dst-run instead of per edge.
__global__ void k_scatter64() {
    constexpr int CHUNK = 16;
    int gid = (blockIdx.x * blockDim.x + threadIdx.x) >> 4;   // 16-lane group
    int p   = threadIdx.x & 15;
    int base = gid * CHUNK;
    if (base >= N_EDGES) return;                              // whole warps exit (1M%32==0)

    float4 rec = __ldg(&g_edge[base + p]);                    // coalesced stage
    int   rs = __float_as_int(rec.x);
    int   rd = __float_as_int(rec.y);
    float rw = rec.z;

    float4 acc = make_float4(0.f, 0.f, 0.f, 0.f);
    int curd = -1;
    for (int j = 0; j < CHUNK; j++) {
        int   s  = __shfl_sync(0xffffffffu, rs, j, 16);
        int   d  = __shfl_sync(0xffffffffu, rd, j, 16);
        float wv = __shfl_sync(0xffffffffu, rw, j, 16);
        if (d != curd) {
            if (curd >= 0) red_add_v4(g_agg + curd * 64 + p * 4, acc);
            acc = make_float4(0.f, 0.f, 0.f, 0.f);
            curd = d;
        }
        uint2 hv = *reinterpret_cast<const uint2*>(&g_h16[s * 64 + p * 4]);
        float2 f0 = __half22float2(*reinterpret_cast<__half2*>(&hv.x));
        float2 f1 = __half22float2(*reinterpret_cast<__half2*>(&hv.y));
        acc.x += wv * f0.x; acc.y += wv * f0.y;
        acc.z += wv * f1.x; acc.w += wv * f1.y;
    }
    if (curd >= 0) red_add_v4(g_agg + curd * 64 + p * 4, acc);
}

// D=32: 8-lane groups, 8 edges/group.
__global__ void k_scatter32(float* __restrict__ OUT) {
    constexpr int CHUNK = 8;
    int gid = (blockIdx.x * blockDim.x + threadIdx.x) >> 3;
    int p   = threadIdx.x & 7;
    int base = gid * CHUNK;
    if (base >= N_EDGES) return;                              // whole warps exit (1M%32==0)

    float4 rec = __ldg(&g_edge[base + p]);
    int   rs = __float_as_int(rec.x);
    int   rd = __float_as_int(rec.y);
    float rw = rec.z;

    float4 acc = make_float4(0.f, 0.f, 0.f, 0.f);
    int curd = -1;
    for (int j = 0; j < CHUNK; j++) {
        int   s  = __shfl_sync(0xffffffffu, rs, j, 8);
        int   d  = __shfl_sync(0xffffffffu, rd, j, 8);
        float wv = __shfl_sync(0xffffffffu, rw, j, 8);
        if (d != curd) {
            if (curd >= 0) red_add_v4(OUT + curd * 32 + p * 4, acc);
            acc = make_float4(0.f, 0.f, 0.f, 0.f);
            curd = d;
        }
        uint2 hv = *reinterpret_cast<const uint2*>(&g_h16[s * 32 + p * 4]);
        float2 f0 = __half22float2(*reinterpret_cast<__half2*>(&hv.x));
        float2 f1 = __half22float2(*reinterpret_cast<__half2*>(&hv.y));
        acc.x += wv * f0.x; acc.y += wv * f0.y;
        acc.z += wv * f1.x; acc.w += wv * f1.y;
    }
    if (curd >= 0) red_add_v4(OUT + curd * 32 + p * 4, acc);
}

// ---------------- finalize layer 2 ----------------
__global__ void k_final2(float* __restrict__ OUT, const float* __restrict__ b) {
    int i = blockIdx.x * blockDim.x + threadIdx.x;
    if (i >= N_NODES * D_OUTF) return;
    int row = i / D_OUTF, col = i % D_OUTF;
    float v = rsqrtf(g_deg[row]) * OUT[i] + b[col];
    OUT[i] = fmaxf(v, 0.0f);
}

extern "C" void kernel_launch(void* const* d_in, const int* in_sizes, int n_in,
                              void* d_out, int out_size) {
    const float* x   = (const float*)d_in[0];
    const int*   ei  = (const int*)  d_in[1];   // [2, E]
    const float* ew  = (const float*)d_in[2];
    const float* W1  = (const float*)d_in[3];
    const float* b1  = (const float*)d_in[4];
    const float* W2  = (const float*)d_in[5];
    const float* b2  = (const float*)d_in[6];
    float*       out = (float*)d_out;

    const int* src = ei;
    const int* dst = ei + N_EDGES;

    // dst-sorted CSR build
    k_zero <<<(N_NODES + 255) / 256, 256>>>();
    k_hist <<<(N_EDGES / 4 + 255) / 256, 256>>>(dst, ew);
    k_scan <<<1, 512>>>();
    k_place<<<(N_EDGES / 4 + 255) / 256, 256>>>(src, dst, ew);

    // ---- layer 1 ----
    k_gemm64<<<(N_NODES + 63) / 64, 128>>>(x, W1);
    k_scatter64<<<(N_EDGES + 255) / 256, 256>>>();            // 1 thread per edge (16/chunk)

    // ---- layer 2 (final1 fused into gemm32 input) ----
    k_gemm32<<<(N_NODES + 127) / 128, 256>>>(W2, b1, out);
    k_scatter32<<<(N_EDGES + 255) / 256, 256>>>(out);         // 1 thread per edge (8/chunk)
    k_final2<<<(N_NODES * D_OUTF + 255) / 256, 256>>>(out, b2);
}

// round 14
// speedup vs baseline: 1.7010x; 1.7010x over previous
#include <cuda_runtime.h>
#include <cuda_fp16.h>

#define N_NODES 50000
#define N_EDGES 1000000
#define D_IN    64
#define D_HID   64
#define D_OUTF  32

// ---- scratch (no allocs). Device globals referenced ONLY in device code. ----
__device__ float  g_deg [N_NODES];
__device__ __align__(16) __half g_h16 [N_NODES * D_HID];   // hs fp16
__device__ __align__(16) __half g_agg [N_NODES * D_HID];   // layer-1 agg, fp16 RMW
__device__ __align__(16) __half g_agg2[N_NODES * D_OUTF];  // layer-2 agg, fp16 RMW

__device__ __forceinline__ unsigned int h2u(__half2 h) {
    return *reinterpret_cast<unsigned int*>(&h);
}

// fp16x2 vector reduction: adds 8 halves (16B) atomically.
__device__ __forceinline__ void red_add_v4h2(__half* p, unsigned int m0, unsigned int m1,
                                             unsigned int m2, unsigned int m3) {
    asm volatile("red.global.add.noftz.v4.f16x2 [%0], {%1, %2, %3, %4};"
                 :: "l"(p), "r"(m0), "r"(m1), "r"(m2), "r"(m3) : "memory");
}

// ---------------- degree ----------------
__global__ void k_deg_init() {
    int i = blockIdx.x * blockDim.x + threadIdx.x;
    if (i < N_NODES) g_deg[i] = 1.0f;          // self-loop weight
}

__global__ void k_deg_count(const int* __restrict__ dst, const float* __restrict__ w) {
    int t = blockIdx.x * blockDim.x + threadIdx.x;
    int e0 = t * 4;
#pragma unroll
    for (int j = 0; j < 4; j++) {
        int e = e0 + j;
        if (e < N_EDGES) atomicAdd(&g_deg[__ldg(&dst[e])], __ldg(&w[e]));
    }
}

// ---------------- GEMM L1 (64->64): 4x8 per thread ----------------
// Writes hs fp16 to g_h16 AND g_agg (self-loop init).
__global__ __launch_bounds__(128) void k_gemm64(
        const float* __restrict__ X, const float* __restrict__ W) {
    constexpr int DI = 64, DO = 64;
    constexpr int TX = 8, ROWS = 64, XS = ROWS + 4;
    __shared__ float Ws [DI * DO];
    __shared__ float xsT[DI * XS];

    const int tid = threadIdx.x;
    const int tx  = tid % TX;
    const int ty  = tid / TX;
    const int blockRow = blockIdx.x * ROWS;

    for (int i = tid; i < DI * DO / 4; i += 128)
        reinterpret_cast<float4*>(Ws)[i] = reinterpret_cast<const float4*>(W)[i];

    for (int i = tid; i < ROWS * (DI / 4); i += 128) {
        int row = i / (DI / 4);
        int c4  = i % (DI / 4);
        int gr  = blockRow + row;
        float4 v = make_float4(0.f, 0.f, 0.f, 0.f);
        if (gr < N_NODES)
            v = reinterpret_cast<const float4*>(X + gr * DI)[c4];
        xsT[(c4 * 4 + 0) * XS + row] = v.x;
        xsT[(c4 * 4 + 1) * XS + row] = v.y;
        xsT[(c4 * 4 + 2) * XS + row] = v.z;
        xsT[(c4 * 4 + 3) * XS + row] = v.w;
    }
    __syncthreads();

    float acc[4][8];
#pragma unroll
    for (int i = 0; i < 4; i++)
#pragma unroll
        for (int j = 0; j < 8; j++) acc[i][j] = 0.0f;

#pragma unroll
    for (int k = 0; k < DI; k++) {
        float4 a  = *reinterpret_cast<const float4*>(&xsT[k * XS + ty * 4]);
        float4 b0 = *reinterpret_cast<const float4*>(&Ws [k * DO + tx * 8]);
        float4 b1 = *reinterpret_cast<const float4*>(&Ws [k * DO + tx * 8 + 4]);
        float av[4] = {a.x, a.y, a.z, a.w};
        float bv[8] = {b0.x, b0.y, b0.z, b0.w, b1.x, b1.y, b1.z, b1.w};
#pragma unroll
        for (int i = 0; i < 4; i++)
#pragma unroll
            for (int j = 0; j < 8; j++)
                acc[i][j] += av[i] * bv[j];
    }

#pragma unroll
    for (int i = 0; i < 4; i++) {
        int row = blockRow + ty * 4 + i;
        if (row >= N_NODES) break;
        float dv = rsqrtf(g_deg[row]);
        float v[8];
#pragma unroll
        for (int j = 0; j < 8; j++) v[j] = dv * acc[i][j];
        uint4 hp;
        hp.x = h2u(__float22half2_rn(make_float2(v[0], v[1])));
        hp.y = h2u(__float22half2_rn(make_float2(v[2], v[3])));
        hp.z = h2u(__float22half2_rn(make_float2(v[4], v[5])));
        hp.w = h2u(__float22half2_rn(make_float2(v[6], v[7])));
        *reinterpret_cast<uint4*>(&g_h16[row * DO + tx * 8]) = hp;
        *reinterpret_cast<uint4*>(&g_agg[row * DO + tx * 8]) = hp;  // self-loop init
    }
}

// ---------------- GEMM L2 (64->32), input fused with final1 ----------------
// Reads fp16 g_agg, applies relu(rsqrt(deg)*v + b1), @W2;
// writes hs2 fp16 to g_h16 (stride 32) and g_agg2 (self-loop init).
__global__ __launch_bounds__(256) void k_gemm32(const float* __restrict__ W,
                                                const float* __restrict__ b1) {
    constexpr int DI = 64, DO = 32;
    constexpr int TX = 8, ROWS = 128, XS = ROWS + 4;
    __shared__ float Ws [DI * DO];
    __shared__ float xsT[DI * XS];

    const int tid = threadIdx.x;
    const int tx  = tid % TX;
    const int ty  = tid / TX;
    const int blockRow = blockIdx.x * ROWS;

    for (int i = tid; i < DI * DO / 4; i += 256)
        reinterpret_cast<float4*>(Ws)[i] = reinterpret_cast<const float4*>(W)[i];

    for (int i = tid; i < ROWS * (DI / 4); i += 256) {
        int row = i / (DI / 4);
        int c4  = i % (DI / 4);
        int gr  = blockRow + row;
        float4 v = make_float4(0.f, 0.f, 0.f, 0.f);
        if (gr < N_NODES) {
            uint2 raw = reinterpret_cast<const uint2*>(g_agg + gr * DI)[c4];
            float2 f0 = __half22float2(*reinterpret_cast<__half2*>(&raw.x));
            float2 f1 = __half22float2(*reinterpret_cast<__half2*>(&raw.y));
            float  dv = rsqrtf(g_deg[gr]);
            float4 bb = __ldg(&reinterpret_cast<const float4*>(b1)[c4]);
            v.x = fmaxf(dv * f0.x + bb.x, 0.0f);
            v.y = fmaxf(dv * f0.y + bb.y, 0.0f);
            v.z = fmaxf(dv * f1.x + bb.z, 0.0f);
            v.w = fmaxf(dv * f1.y + bb.w, 0.0f);
        }
        xsT[(c4 * 4 + 0) * XS + row] = v.x;
        xsT[(c4 * 4 + 1) * XS + row] = v.y;
        xsT[(c4 * 4 + 2) * XS + row] = v.z;
        xsT[(c4 * 4 + 3) * XS + row] = v.w;
    }
    __syncthreads();

    float acc[4][4];
#pragma unroll
    for (int i = 0; i < 4; i++)
#pragma unroll
        for (int j = 0; j < 4; j++) acc[i][j] = 0.0f;

#pragma unroll
    for (int k = 0; k < DI; k++) {
        float4 a = *reinterpret_cast<const float4*>(&xsT[k * XS + ty * 4]);
        float4 b = *reinterpret_cast<const float4*>(&Ws [k * DO + tx * 4]);
        acc[0][0] += a.x * b.x; acc[0][1] += a.x * b.y; acc[0][2] += a.x * b.z; acc[0][3] += a.x * b.w;
        acc[1][0] += a.y * b.x; acc[1][1] += a.y * b.y; acc[1][2] += a.y * b.z; acc[1][3] += a.y * b.w;
        acc[2][0] += a.z * b.x; acc[2][1] += a.z * b.y; acc[2][2] += a.z * b.z; acc[2][3] += a.z * b.w;
        acc[3][0] += a.w * b.x; acc[3][1] += a.w * b.y; acc[3][2] += a.w * b.z; acc[3][3] += a.w * b.w;
    }

#pragma unroll
    for (int i = 0; i < 4; i++) {
        int row = blockRow + ty * 4 + i;
        if (row >= N_NODES) break;
        float dv = rsqrtf(g_deg[row]);
        uint2 hp;
        hp.x = h2u(__float22half2_rn(make_float2(dv * acc[i][0], dv * acc[i][1])));
        hp.y = h2u(__float22half2_rn(make_float2(dv * acc[i][2], dv * acc[i][3])));
        *reinterpret_cast<uint2*>(&g_h16 [row * DO + tx * 4]) = hp;
        *reinterpret_cast<uint2*>(&g_agg2[row * DO + tx * 4]) = hp;  // self-loop init
    }
}

// ---------------- edge scatter: fp16 read + fp16 vector RED ----------------
// D=64: TPE=8, lane covers 8 cols: 1 LDG.128 (8 halves) + 1 RED.v4.f16x2 per edge.
// Two independent edges (opposite halves) per thread.
__global__ void k_scatter64(const int* __restrict__ src,
                            const int* __restrict__ dst,
                            const float* __restrict__ w) {
    constexpr int TPE = 8, HALF = N_EDGES / 2;
    int tid = blockIdx.x * blockDim.x + threadIdx.x;
    int e = tid / TPE;
    int p = tid % TPE;
    if (e >= HALF) return;

#pragma unroll
    for (int half = 0; half < 2; half++) {
        int ee = e + half * HALF;
        int   s  = __ldg(&src[ee]);
        int   d  = __ldg(&dst[ee]);
        float we = __ldg(&w[ee]);
        uint4 hv = *reinterpret_cast<const uint4*>(&g_h16[s * 64 + p * 8]);
        float2 f0 = __half22float2(*reinterpret_cast<__half2*>(&hv.x));
        float2 f1 = __half22float2(*reinterpret_cast<__half2*>(&hv.y));
        float2 f2 = __half22float2(*reinterpret_cast<__half2*>(&hv.z));
        float2 f3 = __half22float2(*reinterpret_cast<__half2*>(&hv.w));
        unsigned int m0 = h2u(__float22half2_rn(make_float2(we*f0.x, we*f0.y)));
        unsigned int m1 = h2u(__float22half2_rn(make_float2(we*f1.x, we*f1.y)));
        unsigned int m2 = h2u(__float22half2_rn(make_float2(we*f2.x, we*f2.y)));
        unsigned int m3 = h2u(__float22half2_rn(make_float2(we*f3.x, we*f3.y)));
        red_add_v4h2(g_agg + d * 64 + p * 8, m0, m1, m2, m3);
    }
}

// D=32: TPE=4, lane covers 8 cols.
__global__ void k_scatter32(const int* __restrict__ src,
                            const int* __restrict__ dst,
                            const float* __restrict__ w) {
    constexpr int TPE = 4, HALF = N_EDGES / 2;
    int tid = blockIdx.x * blockDim.x + threadIdx.x;
    int e = tid / TPE;
    int p = tid % TPE;
    if (e >= HALF) return;

#pragma unroll
    for (int half = 0; half < 2; half++) {
        int ee = e + half * HALF;
        int   s  = __ldg(&src[ee]);
        int   d  = __ldg(&dst[ee]);
        float we = __ldg(&w[ee]);
        uint4 hv = *reinterpret_cast<const uint4*>(&g_h16[s * 32 + p * 8]);
        float2 f0 = __half22float2(*reinterpret_cast<__half2*>(&hv.x));
        float2 f1 = __half22float2(*reinterpret_cast<__half2*>(&hv.y));
        float2 f2 = __half22float2(*reinterpret_cast<__half2*>(&hv.z));
        float2 f3 = __half22float2(*reinterpret_cast<__half2*>(&hv.w));
        unsigned int m0 = h2u(__float22half2_rn(make_float2(we*f0.x, we*f0.y)));
        unsigned int m1 = h2u(__float22half2_rn(make_float2(we*f1.x, we*f1.y)));
        unsigned int m2 = h2u(__float22half2_rn(make_float2(we*f2.x, we*f2.y)));
        unsigned int m3 = h2u(__float22half2_rn(make_float2(we*f3.x, we*f3.y)));
        red_add_v4h2(g_agg2 + d * 32 + p * 8, m0, m1, m2, m3);
    }
}

// ---------------- finalize layer 2: OUT = relu(rsqrt(deg)*agg2 + b2) ----------------
__global__ void k_final2(float* __restrict__ OUT, const float* __restrict__ b) {
    int i = blockIdx.x * blockDim.x + threadIdx.x;
    if (i >= N_NODES * D_OUTF) return;
    int row = i / D_OUTF, col = i % D_OUTF;
    float v = rsqrtf(g_deg[row]) * __half2float(g_agg2[i]) + b[col];
    OUT[i] = fmaxf(v, 0.0f);
}

extern "C" void kernel_launch(void* const* d_in, const int* in_sizes, int n_in,
                              void* d_out, int out_size) {
    const float* x   = (const float*)d_in[0];
    const int*   ei  = (const int*)  d_in[1];   // [2, E]
    const float* ew  = (const float*)d_in[2];
    const float* W1  = (const float*)d_in[3];
    const float* b1  = (const float*)d_in[4];
    const float* W2  = (const float*)d_in[5];
    const float* b2  = (const float*)d_in[6];
    float*       out = (float*)d_out;

    const int* src = ei;
    const int* dst = ei + N_EDGES;

    k_deg_init <<<(N_NODES + 255) / 256, 256>>>();
    k_deg_count<<<(N_EDGES / 4 + 255) / 256, 256>>>(dst, ew);

    // ---- layer 1 ----
    k_gemm64<<<(N_NODES + 63) / 64, 128>>>(x, W1);
    {
        int nthr = (N_EDGES / 2) * 8;
        k_scatter64<<<(nthr + 255) / 256, 256>>>(src, dst, ew);
    }

    // ---- layer 2 (final1 fused into gemm32 input) ----
    k_gemm32<<<(N_NODES + 127) / 128, 256>>>(W2, b1);
    {
        int nthr = (N_EDGES / 2) * 4;
        k_scatter32<<<(nthr + 255) / 256, 256>>>(src, dst, ew);
    }
    k_final2<<<(N_NODES * D_OUTF + 255) / 256, 256>>>(out, b2);
}